// round 14
// baseline (speedup 1.0000x reference)
#include <cuda_runtime.h>
#include <cstdint>

// Problem constants (match reference)
#define NUM_CENTERS 1000
#define CAPACITY    512
#define FEAT_DIM    256
#define BATCH       65536

#define VEC_PER_ROW     (FEAT_DIM / 4)       // 64 float4 per row (1 KB)
#define SAMPLES_PER_BLK 32
#define THREADS         256
#define TOTAL_VEC       (SAMPLES_PER_BLK * VEC_PER_ROW)   // 2048 float4
#define VEC_PER_THREAD  (TOTAL_VEC / THREADS)             // 8

// FINAL kernel - measured optimum, reproduced at 16.86 / 16.90 / 17.57us.
//
// Structure: decoupled pointer-resolve + bulk copy.
//  - Phase A: one warp resolves 32 independent 3-load index chains
//    (tgt -> counts -> rand_idx % cnt), stashing row pointers in SMEM.
//    32 chains in flight amortize the ~1800-cycle dependent-load latency.
//  - Phase B: all 256 threads copy 32 rows (32KB): 8 independent LDG.128
//    per thread (front-batched by ptxas -> MLP=8), each warp covering a
//    contiguous 512B slice of a 1KB row -> perfect 128B-line coalescing.
//  - Stores: __stcs (streaming/evict-first). Write-once output is absorbed
//    by L2 write-back without displacing the graph-replay-resident gather
//    working set (~57MB distinct rows < 126MB L2). Worth 25% alone.
//
// Floor analysis: output writes are irreducible 64MiB/replay -> ~4.0 TB/s
// write bandwidth ~= HBM3e write-direction ceiling; total warm LTS traffic
// ~200MB/replay ~= the ~12 TB/s path-independent LTS cap (so TMA bulk-copy
// cannot help either). Falsified single-variable alternatives (all slower):
// .nc.L2::evict_last v8 loads (25.3), L2 prefetch (21.4), __stwt (21.0),
// __ldcg (18.9), 512-thread blocks (18.5), 256-sample blocks (25.1),
// plain stores (22.6), naive 1-float4/thread (35.3).

__global__ __launch_bounds__(THREADS)
void noise_bank_gather(const int* __restrict__ tgt,
                       const int* __restrict__ ridx,
                       const int* __restrict__ counts,
                       const float4* __restrict__ bank,
                       const float4* __restrict__ fallback,
                       float4* __restrict__ out)
{
    __shared__ const float4* srcs[SAMPLES_PER_BLK];

    const int tid  = threadIdx.x;
    const int base = blockIdx.x * SAMPLES_PER_BLK;

    // Phase A: 32 threads resolve 32 independent source pointers.
    if (tid < SAMPLES_PER_BLK) {
        const int sample = base + tid;
        const int c   = __ldg(&tgt[sample]);
        const int cnt = __ldg(&counts[c]);
        const float4* p;
        if (cnt > 0) {
            const int idx = __ldg(&ridx[sample]) % cnt;
            p = bank + ((int64_t)c * CAPACITY + idx) * VEC_PER_ROW;
        } else {
            p = fallback + (int64_t)sample * VEC_PER_ROW;
        }
        srcs[tid] = p;
    }
    __syncthreads();

    // Phase B: copy 32 rows (32 KB). Each thread: 8 independent LDG.128.
    float4* const out_base = out + (int64_t)base * VEC_PER_ROW;

    float4 v[VEC_PER_THREAD];
    #pragma unroll
    for (int k = 0; k < VEC_PER_THREAD; ++k) {
        const int pos  = k * THREADS + tid;         // 0..2047
        const int s    = pos >> 6;                  // sample within block
        const int lane = pos & (VEC_PER_ROW - 1);   // float4 within row
        v[k] = __ldg(&srcs[s][lane]);
    }
    #pragma unroll
    for (int k = 0; k < VEC_PER_THREAD; ++k) {
        const int pos = k * THREADS + tid;
        __stcs(&out_base[pos], v[k]);
    }
}

extern "C" void kernel_launch(void* const* d_in, const int* in_sizes, int n_in,
                              void* d_out, int out_size)
{
    const int*    tgt      = (const int*)   d_in[0];  // target_center_ids [B]
    const int*    ridx     = (const int*)   d_in[1];  // rand_idx          [B]
    const int*    counts   = (const int*)   d_in[2];  // counts            [NUM_CENTERS]
    const float4* bank     = (const float4*)d_in[3];  // bank [NC, CAP, D]
    const float4* fallback = (const float4*)d_in[4];  // fallback_noise [B, D]
    float4*       out      = (float4*)      d_out;    // [B, D] fp32

    const int grid = BATCH / SAMPLES_PER_BLK;  // 2048
    noise_bank_gather<<<grid, THREADS>>>(tgt, ridx, counts, bank, fallback, out);
}